// round 1
// baseline (speedup 1.0000x reference)
#include <cuda_runtime.h>
#include <cuda_bf16.h>

#define V 50000
#define H 128
#define NDOCS 20000
#define ALPHA 0.7f
#define EPS 1e-5f
#define ROWS 16
#define WPAD 132   // 128 + 4 floats pad -> conflict-free LDS.128 on W rows

// Scratch (allocation-free rule: __device__ globals)
__device__ float g_S1[(size_t)V * H];      // spmm accumulator
__device__ float g_S2[(size_t)V * H];      // gemm output / word_sum
__device__ float g_S3[(size_t)NDOCS * H];  // doc accumulator

// ---------------------------------------------------------------------------
// SpMM via per-edge warp + scalar atomics.
// out[row[e]][:] += val[e] * dense[col[e]][:]
// ---------------------------------------------------------------------------
__global__ void spmm_atomic(const int* __restrict__ row, const int* __restrict__ col,
                            const float* __restrict__ val, const float* __restrict__ dense,
                            float* __restrict__ out, int nnz) {
    int e = (blockIdx.x * blockDim.x + threadIdx.x) >> 5;
    int lane = threadIdx.x & 31;
    if (e >= nnz) return;
    int r = row[e];
    int c = col[e];
    float v = val[e];
    float4 d = ((const float4*)(dense + (size_t)c * H))[lane];
    float* dst = out + (size_t)r * H + lane * 4;
    atomicAdd(dst + 0, v * d.x);
    atomicAdd(dst + 1, v * d.y);
    atomicAdd(dst + 2, v * d.z);
    atomicAdd(dst + 3, v * d.w);
}

// ---------------------------------------------------------------------------
// out = relu(X @ W^T), W is [H,H] row-major, block handles ROWS rows.
// W cached in smem with +4 float row pad (stride WPAD) -> conflict-free LDS.128
// ---------------------------------------------------------------------------
__global__ void gemm_relu(const float* __restrict__ X, const float* __restrict__ W,
                          float* __restrict__ out, int nrows) {
    extern __shared__ float sh[];
    float* Wsh = sh;                   // [H][WPAD]
    float* xs  = sh + H * WPAD;        // [ROWS][H]
    int j = threadIdx.x;               // 0..127

    for (int i = j; i < H * (H / 4); i += blockDim.x) {
        int rw = i >> 5;
        int c4 = i & 31;
        float4 w = ((const float4*)W)[i];
        float* p = Wsh + rw * WPAD + c4 * 4;
        p[0] = w.x; p[1] = w.y; p[2] = w.z; p[3] = w.w;
    }
    int r0 = blockIdx.x * ROWS;
    int nr = min(ROWS, nrows - r0);
    for (int i = j; i < nr * (H / 4); i += blockDim.x)
        ((float4*)xs)[i] = ((const float4*)(X + (size_t)r0 * H))[i];
    __syncthreads();

    float acc[ROWS];
#pragma unroll
    for (int r = 0; r < ROWS; r++) acc[r] = 0.f;

    const float4* X4 = (const float4*)xs;
#pragma unroll 4
    for (int k4 = 0; k4 < H / 4; k4++) {
        float4 w = ((const float4*)(Wsh + j * WPAD))[k4];
#pragma unroll
        for (int r = 0; r < ROWS; r++) {
            float4 x = X4[r * (H / 4) + k4];
            acc[r] += w.x * x.x + w.y * x.y + w.z * x.z + w.w * x.w;
        }
    }
    for (int r = 0; r < nr; r++)
        out[(size_t)(r0 + r) * H + j] = fmaxf(acc[r], 0.f);
}

// ---------------------------------------------------------------------------
// word_sum = layernorm((1-a)*emb + a*relu(Xin @ W2^T)) * g + b + emb
// (the +emb folds the doc_H0 pooling term: X@word_H + X@emb = X@(word_H+emb))
// ---------------------------------------------------------------------------
__global__ void gemm_norm(const float* __restrict__ Xin, const float* __restrict__ W,
                          const float* __restrict__ emb, const float* __restrict__ g,
                          const float* __restrict__ b, float* __restrict__ out,
                          int nrows) {
    extern __shared__ float sh[];
    float* Wsh   = sh;                          // [H][WPAD]
    float* xs    = sh + H * WPAD;               // [ROWS][H]
    float* msh   = xs + ROWS * H;               // [ROWS][H]
    float* stats = msh + ROWS * H;              // [ROWS][2]
    int j = threadIdx.x;

    for (int i = j; i < H * (H / 4); i += blockDim.x) {
        int rw = i >> 5;
        int c4 = i & 31;
        float4 w = ((const float4*)W)[i];
        float* p = Wsh + rw * WPAD + c4 * 4;
        p[0] = w.x; p[1] = w.y; p[2] = w.z; p[3] = w.w;
    }
    int r0 = blockIdx.x * ROWS;
    int nr = min(ROWS, nrows - r0);
    for (int i = j; i < nr * (H / 4); i += blockDim.x)
        ((float4*)xs)[i] = ((const float4*)(Xin + (size_t)r0 * H))[i];
    __syncthreads();

    float acc[ROWS];
#pragma unroll
    for (int r = 0; r < ROWS; r++) acc[r] = 0.f;
    const float4* X4 = (const float4*)xs;
#pragma unroll 4
    for (int k4 = 0; k4 < H / 4; k4++) {
        float4 w = ((const float4*)(Wsh + j * WPAD))[k4];
#pragma unroll
        for (int r = 0; r < ROWS; r++) {
            float4 x = X4[r * (H / 4) + k4];
            acc[r] += w.x * x.x + w.y * x.y + w.z * x.z + w.w * x.w;
        }
    }
#pragma unroll
    for (int r = 0; r < ROWS; r++) {
        float m = 0.f;
        if (r < nr) {
            float e = emb[(size_t)(r0 + r) * H + j];
            m = (1.f - ALPHA) * e + ALPHA * fmaxf(acc[r], 0.f);
        }
        msh[r * H + j] = m;
    }
    __syncthreads();

    // 8 threads per row reduce sum / sumsq
    int rr = j >> 3;
    int sub = j & 7;
    float s = 0.f, s2 = 0.f;
    for (int k = sub; k < H; k += 8) {
        float t = msh[rr * H + k];
        s += t;
        s2 += t * t;
    }
#pragma unroll
    for (int off = 4; off > 0; off >>= 1) {
        s  += __shfl_down_sync(0xffffffffu, s, off);
        s2 += __shfl_down_sync(0xffffffffu, s2, off);
    }
    if (sub == 0) {
        float mu = s * (1.f / H);
        stats[rr * 2 + 0] = mu;
        stats[rr * 2 + 1] = s2 * (1.f / H) - mu * mu;
    }
    __syncthreads();

    float gj = g[j], bj = b[j];
    for (int r = 0; r < nr; r++) {
        float mu = stats[r * 2 + 0];
        float var = stats[r * 2 + 1];
        float m = msh[r * H + j];
        float e = emb[(size_t)(r0 + r) * H + j];
        out[(size_t)(r0 + r) * H + j] =
            (m - mu) * rsqrtf(var + EPS) * gj + bj + e;
    }
}

// ---------------------------------------------------------------------------
// logits = relu(Xin @ mlpW^T + mlp_b) @ clfW^T + clf_b   ([NDOCS,2] out)
// ---------------------------------------------------------------------------
__global__ void head_kernel(const float* __restrict__ Xin, const float* __restrict__ mlpW,
                            const float* __restrict__ mlpb, const float* __restrict__ clfW,
                            const float* __restrict__ clfb, float* __restrict__ out,
                            int nrows) {
    extern __shared__ float sh[];
    float* Wsh  = sh;                  // [H][WPAD]
    float* xs   = sh + H * WPAD;       // [ROWS][H]
    float* psh0 = xs + ROWS * H;       // [ROWS][H]
    float* psh1 = psh0 + ROWS * H;     // [ROWS][H]
    int j = threadIdx.x;

    for (int i = j; i < H * (H / 4); i += blockDim.x) {
        int rw = i >> 5;
        int c4 = i & 31;
        float4 w = ((const float4*)mlpW)[i];
        float* p = Wsh + rw * WPAD + c4 * 4;
        p[0] = w.x; p[1] = w.y; p[2] = w.z; p[3] = w.w;
    }
    int r0 = blockIdx.x * ROWS;
    int nr = min(ROWS, nrows - r0);
    for (int i = j; i < nr * (H / 4); i += blockDim.x)
        ((float4*)xs)[i] = ((const float4*)(Xin + (size_t)r0 * H))[i];
    __syncthreads();

    float acc[ROWS];
#pragma unroll
    for (int r = 0; r < ROWS; r++) acc[r] = 0.f;
    const float4* X4 = (const float4*)xs;
#pragma unroll 4
    for (int k4 = 0; k4 < H / 4; k4++) {
        float4 w = ((const float4*)(Wsh + j * WPAD))[k4];
#pragma unroll
        for (int r = 0; r < ROWS; r++) {
            float4 x = X4[r * (H / 4) + k4];
            acc[r] += w.x * x.x + w.y * x.y + w.z * x.z + w.w * x.w;
        }
    }
    float bj = mlpb[j];
    float c0 = clfW[j];         // clfW[0][j]
    float c1 = clfW[H + j];     // clfW[1][j]
#pragma unroll
    for (int r = 0; r < ROWS; r++) {
        float h = fmaxf(acc[r] + bj, 0.f);
        psh0[r * H + j] = h * c0;
        psh1[r * H + j] = h * c1;
    }
    __syncthreads();

    int rr = j >> 3;
    int sub = j & 7;
    float s0 = 0.f, s1 = 0.f;
    for (int k = sub; k < H; k += 8) {
        s0 += psh0[rr * H + k];
        s1 += psh1[rr * H + k];
    }
#pragma unroll
    for (int off = 4; off > 0; off >>= 1) {
        s0 += __shfl_down_sync(0xffffffffu, s0, off);
        s1 += __shfl_down_sync(0xffffffffu, s1, off);
    }
    if (sub == 0 && rr < nr) {
        out[(size_t)(r0 + rr) * 2 + 0] = s0 + clfb[0];
        out[(size_t)(r0 + rr) * 2 + 1] = s1 + clfb[1];
    }
}

// ---------------------------------------------------------------------------
extern "C" void kernel_launch(void* const* d_in, const int* in_sizes, int n_in,
                              void* d_out, int out_size) {
    const int*   A_row  = (const int*)d_in[0];
    const int*   A_col  = (const int*)d_in[1];
    const float* A_val  = (const float*)d_in[2];
    const int*   X_row  = (const int*)d_in[3];
    const int*   X_col  = (const int*)d_in[4];
    const float* X_val  = (const float*)d_in[5];
    const float* emb_W  = (const float*)d_in[6];
    const float* lin1_W = (const float*)d_in[7];
    const float* lin2_W = (const float*)d_in[8];
    const float* norm_g = (const float*)d_in[9];
    const float* norm_b = (const float*)d_in[10];
    const float* mlp_W  = (const float*)d_in[11];
    const float* mlp_b  = (const float*)d_in[12];
    const float* clf_W  = (const float*)d_in[13];
    const float* clf_b  = (const float*)d_in[14];
    float* out = (float*)d_out;

    int E_nnz = in_sizes[0];
    int X_nnz = in_sizes[3];

    float *S1, *S2, *S3;
    cudaGetSymbolAddress((void**)&S1, g_S1);
    cudaGetSymbolAddress((void**)&S2, g_S2);
    cudaGetSymbolAddress((void**)&S3, g_S3);

    size_t smem_gemm = (H * WPAD + ROWS * H) * sizeof(float);
    size_t smem_norm = (H * WPAD + 2 * ROWS * H + 2 * ROWS) * sizeof(float);
    size_t smem_head = (H * WPAD + 3 * ROWS * H) * sizeof(float);
    cudaFuncSetAttribute(gemm_relu,  cudaFuncAttributeMaxDynamicSharedMemorySize, (int)smem_gemm);
    cudaFuncSetAttribute(gemm_norm,  cudaFuncAttributeMaxDynamicSharedMemorySize, (int)smem_norm);
    cudaFuncSetAttribute(head_kernel, cudaFuncAttributeMaxDynamicSharedMemorySize, (int)smem_head);

    const int TPB = 256;                 // 8 edges per block
    int gA = (E_nnz + 7) / 8;
    int gX = (X_nnz + 7) / 8;
    int gV = (V + ROWS - 1) / ROWS;
    int gD = (NDOCS + ROWS - 1) / ROWS;

    // T1 = A @ emb
    cudaMemsetAsync(S1, 0, (size_t)V * H * sizeof(float));
    spmm_atomic<<<gA, TPB>>>(A_row, A_col, A_val, emb_W, S1, E_nnz);
    // H1 = relu(T1 @ W1^T)
    gemm_relu<<<gV, H, smem_gemm>>>(S1, lin1_W, S2, V);
    // T2 = A @ H1
    cudaMemsetAsync(S1, 0, (size_t)V * H * sizeof(float));
    spmm_atomic<<<gA, TPB>>>(A_row, A_col, A_val, S2, S1, E_nnz);
    // word_sum = layernorm(mix(emb, relu(T2 @ W2^T))) + emb
    gemm_norm<<<gV, H, smem_norm>>>(S1, lin2_W, emb_W, norm_g, norm_b, S2, V);
    // doc = X @ word_sum
    cudaMemsetAsync(S3, 0, (size_t)NDOCS * H * sizeof(float));
    spmm_atomic<<<gX, TPB>>>(X_row, X_col, X_val, S2, S3, X_nnz);
    // logits
    head_kernel<<<gD, H, smem_head>>>(S3, mlp_W, mlp_b, clf_W, clf_b, out, NDOCS);
}

// round 3
// speedup vs baseline: 1.3510x; 1.3510x over previous
#include <cuda_runtime.h>
#include <cuda_bf16.h>

#define V 50000
#define H 128
#define NDOCS 20000
#define ALPHA 0.7f
#define EPS 1e-5f
#define ROWS 64          // rows per block in dense kernels
#define RPT 16           // rows per thread (ROWS / 4 halves)
#define TPB_GEMM 512
#define WPAD 132         // 128 + 4 floats pad -> conflict-free LDS.128 on W rows

// Scratch (allocation-free rule: __device__ globals)
__device__ float g_S1[(size_t)V * H];      // spmm accumulator
__device__ float g_S2[(size_t)V * H];      // gemm output / word_sum
__device__ float g_S3[(size_t)NDOCS * H];  // doc accumulator

// ---------------------------------------------------------------------------
// SpMM via per-edge warp + vectorized red.global.add.v4.f32 (sm_90+).
// out[row[e]][:] += val[e] * dense[col[e]][:]
// ---------------------------------------------------------------------------
__global__ void spmm_atomic(const int* __restrict__ row, const int* __restrict__ col,
                            const float* __restrict__ val, const float* __restrict__ dense,
                            float* __restrict__ out, int nnz) {
    int e = (blockIdx.x * blockDim.x + threadIdx.x) >> 5;
    int lane = threadIdx.x & 31;
    if (e >= nnz) return;
    int r = row[e];
    int c = col[e];
    float v = val[e];
    float4 d = ((const float4*)(dense + (size_t)c * H))[lane];
    float* dst = out + (size_t)r * H + lane * 4;
    asm volatile("red.global.add.v4.f32 [%0], {%1, %2, %3, %4};"
                 :: "l"(dst), "f"(v * d.x), "f"(v * d.y), "f"(v * d.z), "f"(v * d.w)
                 : "memory");
}

// ---------------------------------------------------------------------------
// Shared helpers for dense kernels: 512 threads, 64 rows per block.
// Thread (h, j): h = tid>>7 (0..3), j = tid&127. Handles rows [h*16, h*16+16).
// W cached in smem with +4 float row pad -> conflict-free LDS.128 per warp;
// x row loads are warp-uniform -> smem broadcast (N=1).
// ---------------------------------------------------------------------------
__device__ __forceinline__ void load_W_sh(float* Wsh, const float* __restrict__ W, int tid) {
    for (int i = tid; i < H * (H / 4); i += TPB_GEMM) {
        int rw = i >> 5;
        int c4 = i & 31;
        float4 w = ((const float4*)W)[i];
        float* p = Wsh + rw * WPAD + c4 * 4;
        p[0] = w.x; p[1] = w.y; p[2] = w.z; p[3] = w.w;
    }
}

__device__ __forceinline__ void load_X_sh(float* xs, const float* __restrict__ X,
                                          int r0, int nr, int tid) {
    for (int i = tid; i < ROWS * (H / 4); i += TPB_GEMM) {
        int rr = i / (H / 4);
        float4 x = make_float4(0.f, 0.f, 0.f, 0.f);
        if (rr < nr) x = ((const float4*)(X + (size_t)r0 * H))[i];
        ((float4*)xs)[i] = x;
    }
}

__device__ __forceinline__ void mma_16(float* acc, const float* Wsh, const float* xs,
                                       int j, int h) {
    const float4* X4 = (const float4*)(xs + h * RPT * H);
#pragma unroll 4
    for (int k4 = 0; k4 < H / 4; k4++) {
        float4 w = ((const float4*)(Wsh + j * WPAD))[k4];
#pragma unroll
        for (int r = 0; r < RPT; r++) {
            float4 x = X4[r * (H / 4) + k4];
            acc[r] += w.x * x.x + w.y * x.y + w.z * x.z + w.w * x.w;
        }
    }
}

// ---------------------------------------------------------------------------
// out = relu(X @ W^T)
// ---------------------------------------------------------------------------
__global__ void gemm_relu(const float* __restrict__ X, const float* __restrict__ W,
                          float* __restrict__ out, int nrows) {
    extern __shared__ float sh[];
    float* Wsh = sh;                   // [H][WPAD]
    float* xs  = sh + H * WPAD;        // [ROWS][H]
    int tid = threadIdx.x;
    int j = tid & 127, h = tid >> 7;

    load_W_sh(Wsh, W, tid);
    int r0 = blockIdx.x * ROWS;
    int nr = min(ROWS, nrows - r0);
    load_X_sh(xs, X, r0, nr, tid);
    __syncthreads();

    float acc[RPT];
#pragma unroll
    for (int r = 0; r < RPT; r++) acc[r] = 0.f;
    mma_16(acc, Wsh, xs, j, h);

#pragma unroll
    for (int r = 0; r < RPT; r++) {
        int gr = h * RPT + r;
        if (gr < nr)
            out[(size_t)(r0 + gr) * H + j] = fmaxf(acc[r], 0.f);
    }
}

// ---------------------------------------------------------------------------
// word_sum = layernorm((1-a)*emb + a*relu(Xin @ W2^T)) * g + b + emb
// (+emb folds the doc_H0 pooling term: X@word_H + X@emb = X@(word_H+emb))
// ---------------------------------------------------------------------------
__global__ void gemm_norm(const float* __restrict__ Xin, const float* __restrict__ W,
                          const float* __restrict__ emb, const float* __restrict__ g,
                          const float* __restrict__ b, float* __restrict__ out,
                          int nrows) {
    extern __shared__ float sh[];
    float* Wsh   = sh;                          // [H][WPAD]
    float* xs    = sh + H * WPAD;               // [ROWS][H]
    float* msh   = xs + ROWS * H;               // [ROWS][H]
    float* stats = msh + ROWS * H;              // [ROWS][2]
    int tid = threadIdx.x;
    int j = tid & 127, h = tid >> 7;

    load_W_sh(Wsh, W, tid);
    int r0 = blockIdx.x * ROWS;
    int nr = min(ROWS, nrows - r0);
    load_X_sh(xs, Xin, r0, nr, tid);
    __syncthreads();

    float acc[RPT];
#pragma unroll
    for (int r = 0; r < RPT; r++) acc[r] = 0.f;
    mma_16(acc, Wsh, xs, j, h);

#pragma unroll
    for (int r = 0; r < RPT; r++) {
        int gr = h * RPT + r;
        float m = 0.f;
        if (gr < nr) {
            float e = emb[(size_t)(r0 + gr) * H + j];
            m = (1.f - ALPHA) * e + ALPHA * fmaxf(acc[r], 0.f);
        }
        msh[gr * H + j] = m;
    }
    __syncthreads();

    // 8 threads per row reduce sum / sumsq (512 threads -> 64 rows)
    int rr = tid >> 3;
    int sub = tid & 7;
    float s = 0.f, s2 = 0.f;
    for (int k = sub; k < H; k += 8) {
        float t = msh[rr * H + k];
        s += t;
        s2 += t * t;
    }
#pragma unroll
    for (int off = 4; off > 0; off >>= 1) {
        s  += __shfl_down_sync(0xffffffffu, s, off);
        s2 += __shfl_down_sync(0xffffffffu, s2, off);
    }
    if (sub == 0) {
        float mu = s * (1.f / H);
        stats[rr * 2 + 0] = mu;
        stats[rr * 2 + 1] = s2 * (1.f / H) - mu * mu;
    }
    __syncthreads();

    float gj = g[j], bj = b[j];
#pragma unroll
    for (int r = 0; r < RPT; r++) {
        int gr = h * RPT + r;
        if (gr < nr) {
            float mu = stats[gr * 2 + 0];
            float var = stats[gr * 2 + 1];
            float m = msh[gr * H + j];
            float e = emb[(size_t)(r0 + gr) * H + j];
            out[(size_t)(r0 + gr) * H + j] =
                (m - mu) * rsqrtf(var + EPS) * gj + bj + e;
        }
    }
}

// ---------------------------------------------------------------------------
// logits = relu(Xin @ mlpW^T + mlp_b) @ clfW^T + clf_b   ([NDOCS,2] out)
// ---------------------------------------------------------------------------
__global__ void head_kernel(const float* __restrict__ Xin, const float* __restrict__ mlpW,
                            const float* __restrict__ mlpb, const float* __restrict__ clfW,
                            const float* __restrict__ clfb, float* __restrict__ out,
                            int nrows) {
    extern __shared__ float sh[];
    float* Wsh  = sh;                  // [H][WPAD]
    float* xs   = sh + H * WPAD;       // [ROWS][H]
    float* psh0 = xs + ROWS * H;       // [ROWS][H]
    float* psh1 = psh0 + ROWS * H;     // [ROWS][H]
    int tid = threadIdx.x;
    int j = tid & 127, h = tid >> 7;

    load_W_sh(Wsh, mlpW, tid);
    int r0 = blockIdx.x * ROWS;
    int nr = min(ROWS, nrows - r0);
    load_X_sh(xs, Xin, r0, nr, tid);
    __syncthreads();

    float acc[RPT];
#pragma unroll
    for (int r = 0; r < RPT; r++) acc[r] = 0.f;
    mma_16(acc, Wsh, xs, j, h);

    float bj = mlpb[j];
    float c0 = clfW[j];         // clfW[0][j]
    float c1 = clfW[H + j];     // clfW[1][j]
#pragma unroll
    for (int r = 0; r < RPT; r++) {
        int gr = h * RPT + r;
        float hh = fmaxf(acc[r] + bj, 0.f);
        psh0[gr * H + j] = hh * c0;
        psh1[gr * H + j] = hh * c1;
    }
    __syncthreads();

    int rr = tid >> 3;
    int sub = tid & 7;
    float s0 = 0.f, s1 = 0.f;
    for (int k = sub; k < H; k += 8) {
        s0 += psh0[rr * H + k];
        s1 += psh1[rr * H + k];
    }
#pragma unroll
    for (int off = 4; off > 0; off >>= 1) {
        s0 += __shfl_down_sync(0xffffffffu, s0, off);
        s1 += __shfl_down_sync(0xffffffffu, s1, off);
    }
    if (sub == 0 && rr < nr) {
        out[(size_t)(r0 + rr) * 2 + 0] = s0 + clfb[0];
        out[(size_t)(r0 + rr) * 2 + 1] = s1 + clfb[1];
    }
}

// ---------------------------------------------------------------------------
extern "C" void kernel_launch(void* const* d_in, const int* in_sizes, int n_in,
                              void* d_out, int out_size) {
    const int*   A_row  = (const int*)d_in[0];
    const int*   A_col  = (const int*)d_in[1];
    const float* A_val  = (const float*)d_in[2];
    const int*   X_row  = (const int*)d_in[3];
    const int*   X_col  = (const int*)d_in[4];
    const float* X_val  = (const float*)d_in[5];
    const float* emb_W  = (const float*)d_in[6];
    const float* lin1_W = (const float*)d_in[7];
    const float* lin2_W = (const float*)d_in[8];
    const float* norm_g = (const float*)d_in[9];
    const float* norm_b = (const float*)d_in[10];
    const float* mlp_W  = (const float*)d_in[11];
    const float* mlp_b  = (const float*)d_in[12];
    const float* clf_W  = (const float*)d_in[13];
    const float* clf_b  = (const float*)d_in[14];
    float* out = (float*)d_out;

    int E_nnz = in_sizes[0];
    int X_nnz = in_sizes[3];

    float *S1, *S2, *S3;
    cudaGetSymbolAddress((void**)&S1, g_S1);
    cudaGetSymbolAddress((void**)&S2, g_S2);
    cudaGetSymbolAddress((void**)&S3, g_S3);

    size_t smem_gemm = (H * WPAD + ROWS * H) * sizeof(float);
    size_t smem_norm = (H * WPAD + 2 * ROWS * H + 2 * ROWS) * sizeof(float);
    size_t smem_head = (H * WPAD + 3 * ROWS * H) * sizeof(float);
    cudaFuncSetAttribute(gemm_relu,  cudaFuncAttributeMaxDynamicSharedMemorySize, (int)smem_gemm);
    cudaFuncSetAttribute(gemm_norm,  cudaFuncAttributeMaxDynamicSharedMemorySize, (int)smem_norm);
    cudaFuncSetAttribute(head_kernel, cudaFuncAttributeMaxDynamicSharedMemorySize, (int)smem_head);

    const int TPB = 256;                 // 8 edges per block
    int gA = (E_nnz + 7) / 8;
    int gX = (X_nnz + 7) / 8;
    int gV = (V + ROWS - 1) / ROWS;
    int gD = (NDOCS + ROWS - 1) / ROWS;

    // T1 = A @ emb
    cudaMemsetAsync(S1, 0, (size_t)V * H * sizeof(float));
    spmm_atomic<<<gA, TPB>>>(A_row, A_col, A_val, emb_W, S1, E_nnz);
    // H1 = relu(T1 @ W1^T)
    gemm_relu<<<gV, TPB_GEMM, smem_gemm>>>(S1, lin1_W, S2, V);
    // T2 = A @ H1
    cudaMemsetAsync(S1, 0, (size_t)V * H * sizeof(float));
    spmm_atomic<<<gA, TPB>>>(A_row, A_col, A_val, S2, S1, E_nnz);
    // word_sum = layernorm(mix(emb, relu(T2 @ W2^T))) + emb
    gemm_norm<<<gV, TPB_GEMM, smem_norm>>>(S1, lin2_W, emb_W, norm_g, norm_b, S2, V);
    // doc = X @ word_sum
    cudaMemsetAsync(S3, 0, (size_t)NDOCS * H * sizeof(float));
    spmm_atomic<<<gX, TPB>>>(X_row, X_col, X_val, S2, S3, X_nnz);
    // logits
    head_kernel<<<gD, TPB_GEMM, smem_head>>>(S3, mlp_W, mlp_b, clf_W, clf_b, out, NDOCS);
}

// round 5
// speedup vs baseline: 3.3103x; 2.4501x over previous
#include <cuda_runtime.h>
#include <cuda_bf16.h>

#define V 50000
#define H 128
#define NDOCS 20000
#define E_MAX 1600000
#define ALPHA 0.7f
#define EPS 1e-5f
#define ROWS 32          // rows per block in dense kernels
#define RPT 8            // rows per thread group
#define TPB_GEMM 512
#define WPAD 132         // 128 + 4 floats pad

// Scratch (allocation-free rule: __device__ globals)
__device__ float g_S1[(size_t)V * H];
__device__ float g_S2[(size_t)V * H];
__device__ float g_S3[(size_t)NDOCS * H];
__device__ int   g_rptrA[V + 1];
__device__ int   g_rptrX[NDOCS + 1];
__device__ int2  g_edgeA[E_MAX];          // (col, val-bits) sorted by row
__device__ int2  g_edgeX[E_MAX];
__device__ int   g_cnt[V + 1];            // histogram / scatter offsets
__device__ int   g_bsums[1024];

// ---------------------------------------------------------------------------
// CSR build: histogram -> block scan -> scatter
// ---------------------------------------------------------------------------
__global__ void hist_kernel(const int* __restrict__ row, int* __restrict__ cnt, int nnz) {
    int e = blockIdx.x * blockDim.x + threadIdx.x;
    if (e < nnz) atomicAdd(&cnt[row[e]], 1);
}

__global__ void scan1(const int* __restrict__ cnt, int* __restrict__ rptr,
                      int* __restrict__ bsums, int n) {
    __shared__ int sh[1024];
    int tid = threadIdx.x;
    int gid = blockIdx.x * 1024 + tid;
    int x = (gid < n) ? cnt[gid] : 0;
    sh[tid] = x;
    __syncthreads();
    for (int off = 1; off < 1024; off <<= 1) {
        int t = (tid >= off) ? sh[tid - off] : 0;
        __syncthreads();
        sh[tid] += t;
        __syncthreads();
    }
    if (gid < n) rptr[gid] = sh[tid] - x;       // exclusive within block
    if (tid == 1023) bsums[blockIdx.x] = sh[tid];
}

__global__ void scan2(int* __restrict__ bsums, int nb) {
    __shared__ int sh[1024];
    int tid = threadIdx.x;
    int x = (tid < nb) ? bsums[tid] : 0;
    sh[tid] = x;
    __syncthreads();
    for (int off = 1; off < 1024; off <<= 1) {
        int t = (tid >= off) ? sh[tid - off] : 0;
        __syncthreads();
        sh[tid] += t;
        __syncthreads();
    }
    if (tid < nb) bsums[tid] = sh[tid] - x;     // exclusive
}

__global__ void scan3(int* __restrict__ rptr, const int* __restrict__ bsums,
                      int* __restrict__ woff, int n, int nnz) {
    int gid = blockIdx.x * 1024 + threadIdx.x;
    if (gid < n) {
        int v = rptr[gid] + bsums[blockIdx.x];
        rptr[gid] = v;
        woff[gid] = v;
    }
    if (gid == 0) rptr[n] = nnz;
}

__global__ void scatter_kernel(const int* __restrict__ row, const int* __restrict__ col,
                               const float* __restrict__ val, int* __restrict__ woff,
                               int2* __restrict__ edges, int nnz) {
    int e = blockIdx.x * blockDim.x + threadIdx.x;
    if (e >= nnz) return;
    int r = row[e];
    int p = atomicAdd(&woff[r], 1);
    edges[p] = make_int2(col[e], __float_as_int(val[e]));
}

// ---------------------------------------------------------------------------
// CSR SpMM: one warp per row, register accumulation, single store per row.
// out[r][:] = sum_e val[e] * dense[col[e]][:]
// ---------------------------------------------------------------------------
__global__ void spmm_csr(const int* __restrict__ rptr, const int2* __restrict__ edges,
                         const float* __restrict__ dense, float* __restrict__ out,
                         int nrows) {
    int r = blockIdx.x * 8 + (threadIdx.x >> 5);
    int lane = threadIdx.x & 31;
    if (r >= nrows) return;
    int s = rptr[r], e = rptr[r + 1];
    const float4* d4 = (const float4*)dense;
    float4 acc = make_float4(0.f, 0.f, 0.f, 0.f);
    int i = s;
    for (; i + 4 <= e; i += 4) {
        int2 c0 = edges[i + 0];
        int2 c1 = edges[i + 1];
        int2 c2 = edges[i + 2];
        int2 c3 = edges[i + 3];
        float4 d0 = d4[(size_t)c0.x * 32 + lane];
        float4 d1 = d4[(size_t)c1.x * 32 + lane];
        float4 d2 = d4[(size_t)c2.x * 32 + lane];
        float4 d3 = d4[(size_t)c3.x * 32 + lane];
        float v0 = __int_as_float(c0.y), v1 = __int_as_float(c1.y);
        float v2 = __int_as_float(c2.y), v3 = __int_as_float(c3.y);
        acc.x = fmaf(v0, d0.x, acc.x); acc.y = fmaf(v0, d0.y, acc.y);
        acc.z = fmaf(v0, d0.z, acc.z); acc.w = fmaf(v0, d0.w, acc.w);
        acc.x = fmaf(v1, d1.x, acc.x); acc.y = fmaf(v1, d1.y, acc.y);
        acc.z = fmaf(v1, d1.z, acc.z); acc.w = fmaf(v1, d1.w, acc.w);
        acc.x = fmaf(v2, d2.x, acc.x); acc.y = fmaf(v2, d2.y, acc.y);
        acc.z = fmaf(v2, d2.z, acc.z); acc.w = fmaf(v2, d2.w, acc.w);
        acc.x = fmaf(v3, d3.x, acc.x); acc.y = fmaf(v3, d3.y, acc.y);
        acc.z = fmaf(v3, d3.z, acc.z); acc.w = fmaf(v3, d3.w, acc.w);
    }
    for (; i < e; i++) {
        int2 c = edges[i];
        float4 d = d4[(size_t)c.x * 32 + lane];
        float v = __int_as_float(c.y);
        acc.x = fmaf(v, d.x, acc.x); acc.y = fmaf(v, d.y, acc.y);
        acc.z = fmaf(v, d.z, acc.z); acc.w = fmaf(v, d.w, acc.w);
    }
    ((float4*)out)[(size_t)r * 32 + lane] = acc;
}

// ---------------------------------------------------------------------------
// Dense kernel helpers: 512 threads, 32 rows per block, 2 blocks/SM.
// Thread (h, j): h = tid>>7 (0..3) handles rows [h*8, h*8+8), j = tid&127.
// ---------------------------------------------------------------------------
__device__ __forceinline__ void load_W_sh(float* Wsh, const float* __restrict__ W, int tid) {
    for (int i = tid; i < H * (H / 4); i += TPB_GEMM) {
        int rw = i >> 5;
        int c4 = i & 31;
        float4 w = ((const float4*)W)[i];
        float* p = Wsh + rw * WPAD + c4 * 4;
        p[0] = w.x; p[1] = w.y; p[2] = w.z; p[3] = w.w;
    }
}

__device__ __forceinline__ void load_X_sh(float* xs, const float* __restrict__ X,
                                          int r0, int nr, int tid) {
    for (int i = tid; i < ROWS * (H / 4); i += TPB_GEMM) {
        int rr = i / (H / 4);
        float4 x = make_float4(0.f, 0.f, 0.f, 0.f);
        if (rr < nr) x = ((const float4*)(X + (size_t)r0 * H))[i];
        ((float4*)xs)[i] = x;
    }
}

__device__ __forceinline__ void mma_8(float* acc, const float* Wsh, const float* xs,
                                      int j, int h) {
    const float4* X4 = (const float4*)(xs + h * RPT * H);
#pragma unroll 4
    for (int k4 = 0; k4 < H / 4; k4++) {
        float4 w = ((const float4*)(Wsh + j * WPAD))[k4];
#pragma unroll
        for (int r = 0; r < RPT; r++) {
            float4 x = X4[r * (H / 4) + k4];
            acc[r] += w.x * x.x + w.y * x.y + w.z * x.z + w.w * x.w;
        }
    }
}

// ---------------------------------------------------------------------------
// out = relu(X @ W^T)
// ---------------------------------------------------------------------------
__global__ __launch_bounds__(TPB_GEMM, 2)
void gemm_relu(const float* __restrict__ X, const float* __restrict__ W,
               float* __restrict__ out, int nrows) {
    extern __shared__ float sh[];
    float* Wsh = sh;                   // [H][WPAD]
    float* xs  = sh + H * WPAD;        // [ROWS][H]
    int tid = threadIdx.x;
    int j = tid & 127, h = tid >> 7;

    load_W_sh(Wsh, W, tid);
    int r0 = blockIdx.x * ROWS;
    int nr = min(ROWS, nrows - r0);
    load_X_sh(xs, X, r0, nr, tid);
    __syncthreads();

    float acc[RPT];
#pragma unroll
    for (int r = 0; r < RPT; r++) acc[r] = 0.f;
    mma_8(acc, Wsh, xs, j, h);

#pragma unroll
    for (int r = 0; r < RPT; r++) {
        int gr = h * RPT + r;
        if (gr < nr)
            out[(size_t)(r0 + gr) * H + j] = fmaxf(acc[r], 0.f);
    }
}

// ---------------------------------------------------------------------------
// word_sum = layernorm((1-a)*emb + a*relu(Xin @ W2^T)) * g + b + emb
// (+emb folds doc_H0: X@word_H + X@emb = X@(word_H+emb))
// ---------------------------------------------------------------------------
__global__ __launch_bounds__(TPB_GEMM, 2)
void gemm_norm(const float* __restrict__ Xin, const float* __restrict__ W,
               const float* __restrict__ emb, const float* __restrict__ g,
               const float* __restrict__ b, float* __restrict__ out, int nrows) {
    extern __shared__ float sh[];
    float* Wsh   = sh;                          // [H][WPAD]
    float* xs    = sh + H * WPAD;               // [ROWS][H], reused as msh
    float* stats = xs + ROWS * H;               // [ROWS][2]
    int tid = threadIdx.x;
    int j = tid & 127, h = tid >> 7;

    load_W_sh(Wsh, W, tid);
    int r0 = blockIdx.x * ROWS;
    int nr = min(ROWS, nrows - r0);
    load_X_sh(xs, Xin, r0, nr, tid);
    __syncthreads();

    float acc[RPT];
#pragma unroll
    for (int r = 0; r < RPT; r++) acc[r] = 0.f;
    mma_8(acc, Wsh, xs, j, h);
    __syncthreads();                            // all reads of xs done

    float* msh = xs;
#pragma unroll
    for (int r = 0; r < RPT; r++) {
        int gr = h * RPT + r;
        float m = 0.f;
        if (gr < nr) {
            float e = emb[(size_t)(r0 + gr) * H + j];
            m = (1.f - ALPHA) * e + ALPHA * fmaxf(acc[r], 0.f);
        }
        msh[gr * H + j] = m;
    }
    __syncthreads();

    // 16 threads per row reduce sum / sumsq (512 threads -> 32 rows)
    int rr = tid >> 4;
    int sub = tid & 15;
    float s = 0.f, s2 = 0.f;
    for (int k = sub; k < H; k += 16) {
        float t = msh[rr * H + k];
        s += t;
        s2 += t * t;
    }
#pragma unroll
    for (int off = 8; off > 0; off >>= 1) {
        s  += __shfl_down_sync(0xffffffffu, s, off, 16);
        s2 += __shfl_down_sync(0xffffffffu, s2, off, 16);
    }
    if (sub == 0) {
        float mu = s * (1.f / H);
        stats[rr * 2 + 0] = mu;
        stats[rr * 2 + 1] = s2 * (1.f / H) - mu * mu;
    }
    __syncthreads();

    float gj = g[j], bj = b[j];
#pragma unroll
    for (int r = 0; r < RPT; r++) {
        int gr = h * RPT + r;
        if (gr < nr) {
            float mu  = stats[gr * 2 + 0];
            float var = stats[gr * 2 + 1];
            float m = msh[gr * H + j];
            float e = emb[(size_t)(r0 + gr) * H + j];
            out[(size_t)(r0 + gr) * H + j] =
                (m - mu) * rsqrtf(var + EPS) * gj + bj + e;
        }
    }
}

// ---------------------------------------------------------------------------
// logits = relu(Xin @ mlpW^T + mlp_b) @ clfW^T + clf_b   ([NDOCS,2] out)
// ---------------------------------------------------------------------------
__global__ __launch_bounds__(TPB_GEMM, 2)
void head_kernel(const float* __restrict__ Xin, const float* __restrict__ mlpW,
                 const float* __restrict__ mlpb, const float* __restrict__ clfW,
                 const float* __restrict__ clfb, float* __restrict__ out, int nrows) {
    extern __shared__ float sh[];
    float* Wsh  = sh;                  // [H][WPAD]
    float* xs   = sh + H * WPAD;       // [ROWS][H], reused as psh0
    float* psh1 = xs + ROWS * H;       // [ROWS][H]
    int tid = threadIdx.x;
    int j = tid & 127, h = tid >> 7;

    load_W_sh(Wsh, mlpW, tid);
    int r0 = blockIdx.x * ROWS;
    int nr = min(ROWS, nrows - r0);
    load_X_sh(xs, Xin, r0, nr, tid);
    __syncthreads();

    float acc[RPT];
#pragma unroll
    for (int r = 0; r < RPT; r++) acc[r] = 0.f;
    mma_8(acc, Wsh, xs, j, h);
    __syncthreads();                   // all reads of xs done

    float* psh0 = xs;
    float bj = mlpb[j];
    float c0 = clfW[j];
    float c1 = clfW[H + j];
#pragma unroll
    for (int r = 0; r < RPT; r++) {
        int gr = h * RPT + r;
        float hh = fmaxf(acc[r] + bj, 0.f);
        psh0[gr * H + j] = hh * c0;
        psh1[gr * H + j] = hh * c1;
    }
    __syncthreads();

    int rr = tid >> 4;
    int sub = tid & 15;
    float s0 = 0.f, s1 = 0.f;
    for (int k = sub; k < H; k += 16) {
        s0 += psh0[rr * H + k];
        s1 += psh1[rr * H + k];
    }
#pragma unroll
    for (int off = 8; off > 0; off >>= 1) {
        s0 += __shfl_down_sync(0xffffffffu, s0, off, 16);
        s1 += __shfl_down_sync(0xffffffffu, s1, off, 16);
    }
    if (sub == 0 && rr < nr) {
        out[(size_t)(r0 + rr) * 2 + 0] = s0 + clfb[0];
        out[(size_t)(r0 + rr) * 2 + 1] = s1 + clfb[1];
    }
}

// ---------------------------------------------------------------------------
extern "C" void kernel_launch(void* const* d_in, const int* in_sizes, int n_in,
                              void* d_out, int out_size) {
    const int*   A_row  = (const int*)d_in[0];
    const int*   A_col  = (const int*)d_in[1];
    const float* A_val  = (const float*)d_in[2];
    const int*   X_row  = (const int*)d_in[3];
    const int*   X_col  = (const int*)d_in[4];
    const float* X_val  = (const float*)d_in[5];
    const float* emb_W  = (const float*)d_in[6];
    const float* lin1_W = (const float*)d_in[7];
    const float* lin2_W = (const float*)d_in[8];
    const float* norm_g = (const float*)d_in[9];
    const float* norm_b = (const float*)d_in[10];
    const float* mlp_W  = (const float*)d_in[11];
    const float* mlp_b  = (const float*)d_in[12];
    const float* clf_W  = (const float*)d_in[13];
    const float* clf_b  = (const float*)d_in[14];
    float* out = (float*)d_out;

    int E_nnz = in_sizes[0];
    int X_nnz = in_sizes[3];

    float *S1, *S2, *S3;
    int *rptrA, *rptrX, *cnt, *bsums;
    int2 *edgeA, *edgeX;
    cudaGetSymbolAddress((void**)&S1, g_S1);
    cudaGetSymbolAddress((void**)&S2, g_S2);
    cudaGetSymbolAddress((void**)&S3, g_S3);
    cudaGetSymbolAddress((void**)&rptrA, g_rptrA);
    cudaGetSymbolAddress((void**)&rptrX, g_rptrX);
    cudaGetSymbolAddress((void**)&cnt,   g_cnt);
    cudaGetSymbolAddress((void**)&bsums, g_bsums);
    cudaGetSymbolAddress((void**)&edgeA, g_edgeA);
    cudaGetSymbolAddress((void**)&edgeX, g_edgeX);

    size_t smem_gemm = (H * WPAD + ROWS * H) * sizeof(float);
    size_t smem_norm = (H * WPAD + ROWS * H + 2 * ROWS) * sizeof(float);
    size_t smem_head = (H * WPAD + 2 * ROWS * H) * sizeof(float);
    cudaFuncSetAttribute(gemm_relu,   cudaFuncAttributeMaxDynamicSharedMemorySize, (int)smem_gemm);
    cudaFuncSetAttribute(gemm_norm,   cudaFuncAttributeMaxDynamicSharedMemorySize, (int)smem_norm);
    cudaFuncSetAttribute(head_kernel, cudaFuncAttributeMaxDynamicSharedMemorySize, (int)smem_head);

    int nbA = (V + 1023) / 1024;        // 49
    int nbX = (NDOCS + 1023) / 1024;    // 20
    int gEA = (E_nnz + 255) / 256;
    int gEX = (X_nnz + 255) / 256;
    int gV  = (V + ROWS - 1) / ROWS;
    int gD  = (NDOCS + ROWS - 1) / ROWS;
    int gRA = (V + 7) / 8;              // spmm_csr: 8 rows/block
    int gRX = (NDOCS + 7) / 8;

    // ---- Build CSR for A (used by both graph SpMMs) ----
    cudaMemsetAsync(cnt, 0, (size_t)V * sizeof(int));
    hist_kernel<<<gEA, 256>>>(A_row, cnt, E_nnz);
    scan1<<<nbA, 1024>>>(cnt, rptrA, bsums, V);
    scan2<<<1, 1024>>>(bsums, nbA);
    scan3<<<nbA, 1024>>>(rptrA, bsums, cnt, V, E_nnz);
    scatter_kernel<<<gEA, 256>>>(A_row, A_col, A_val, cnt, edgeA, E_nnz);

    // ---- Build CSR for X ----
    cudaMemsetAsync(cnt, 0, (size_t)NDOCS * sizeof(int));
    hist_kernel<<<gEX, 256>>>(X_row, cnt, X_nnz);
    scan1<<<nbX, 1024>>>(cnt, rptrX, bsums, NDOCS);
    scan2<<<1, 1024>>>(bsums, nbX);
    scan3<<<nbX, 1024>>>(rptrX, bsums, cnt, NDOCS, X_nnz);
    scatter_kernel<<<gEX, 256>>>(X_row, X_col, X_val, cnt, edgeX, X_nnz);

    // ---- Pipeline ----
    // T1 = A @ emb
    spmm_csr<<<gRA, 256>>>(rptrA, edgeA, emb_W, S1, V);
    // H1 = relu(T1 @ W1^T)
    gemm_relu<<<gV, TPB_GEMM, smem_gemm>>>(S1, lin1_W, S2, V);
    // T2 = A @ H1
    spmm_csr<<<gRA, 256>>>(rptrA, edgeA, S2, S1, V);
    // word_sum = layernorm(mix(emb, relu(T2 @ W2^T))) + emb
    gemm_norm<<<gV, TPB_GEMM, smem_norm>>>(S1, lin2_W, emb_W, norm_g, norm_b, S2, V);
    // doc = X @ word_sum
    spmm_csr<<<gRX, 256>>>(rptrX, edgeX, S2, S3, NDOCS);
    // logits
    head_kernel<<<gD, TPB_GEMM, smem_head>>>(S3, mlp_W, mlp_b, clf_W, clf_b, out, NDOCS);
}

// round 7
// speedup vs baseline: 3.5413x; 1.0698x over previous
#include <cuda_runtime.h>
#include <cuda_bf16.h>

#define V 50000
#define H 128
#define NDOCS 20000
#define E_MAX 1600000
#define ALPHA 0.7f
#define EPS 1e-5f
#define ROWS 32          // rows per block in dense kernels
#define RPT 8            // rows per thread group
#define TPB_GEMM 512
#define WPAD 132         // 128 + 4 floats pad

// Scratch (allocation-free rule: __device__ globals)
__device__ float g_S1[(size_t)V * H];             // fp32 spmm accumulator
__device__ float g_S3[(size_t)NDOCS * H];         // doc accumulator
__device__ __nv_bfloat16 g_B1[(size_t)V * H];     // bf16 dense operand staging
__device__ int   g_rptrA[V + 1];
__device__ int   g_rptrX[NDOCS + 1];
__device__ int2  g_edgeA[E_MAX];                  // (col, val-bits) sorted by row
__device__ int2  g_edgeX[E_MAX];
__device__ int   g_cntA[V + 1];
__device__ int   g_cntX[NDOCS + 1];
__device__ int   g_bsumsA[1024];
__device__ int   g_bsumsX[1024];

// ---------------------------------------------------------------------------
// fp32 -> bf16 conversion (vectorized: float4 in, 4x bf16 out)
// ---------------------------------------------------------------------------
__global__ void f2bf_kernel(const float* __restrict__ in, __nv_bfloat16* __restrict__ out,
                            int n4) {
    int i = blockIdx.x * blockDim.x + threadIdx.x;
    if (i >= n4) return;
    float4 f = ((const float4*)in)[i];
    __nv_bfloat162 lo = __floats2bfloat162_rn(f.x, f.y);
    __nv_bfloat162 hi = __floats2bfloat162_rn(f.z, f.w);
    uint2 u;
    u.x = *(unsigned*)&lo;
    u.y = *(unsigned*)&hi;
    ((uint2*)out)[i] = u;
}

// ---------------------------------------------------------------------------
// CSR build: histogram -> block scan -> scatter
// ---------------------------------------------------------------------------
__global__ void hist_kernel(const int* __restrict__ row, int* __restrict__ cnt, int nnz) {
    int e = blockIdx.x * blockDim.x + threadIdx.x;
    if (e < nnz) atomicAdd(&cnt[row[e]], 1);
}

__global__ void scan1(const int* __restrict__ cnt, int* __restrict__ rptr,
                      int* __restrict__ bsums, int n) {
    __shared__ int sh[1024];
    int tid = threadIdx.x;
    int gid = blockIdx.x * 1024 + tid;
    int x = (gid < n) ? cnt[gid] : 0;
    sh[tid] = x;
    __syncthreads();
    for (int off = 1; off < 1024; off <<= 1) {
        int t = (tid >= off) ? sh[tid - off] : 0;
        __syncthreads();
        sh[tid] += t;
        __syncthreads();
    }
    if (gid < n) rptr[gid] = sh[tid] - x;       // exclusive within block
    if (tid == 1023) bsums[blockIdx.x] = sh[tid];
}

__global__ void scan2(int* __restrict__ bsums, int nb) {
    __shared__ int sh[1024];
    int tid = threadIdx.x;
    int x = (tid < nb) ? bsums[tid] : 0;
    sh[tid] = x;
    __syncthreads();
    for (int off = 1; off < 1024; off <<= 1) {
        int t = (tid >= off) ? sh[tid - off] : 0;
        __syncthreads();
        sh[tid] += t;
        __syncthreads();
    }
    if (tid < nb) bsums[tid] = sh[tid] - x;     // exclusive
}

__global__ void scan3(int* __restrict__ rptr, const int* __restrict__ bsums,
                      int* __restrict__ woff, int n, int nnz) {
    int gid = blockIdx.x * 1024 + threadIdx.x;
    if (gid < n) {
        int v = rptr[gid] + bsums[blockIdx.x];
        rptr[gid] = v;
        woff[gid] = v;
    }
    if (gid == 0) rptr[n] = nnz;
}

__global__ void scatter_kernel(const int* __restrict__ row, const int* __restrict__ col,
                               const float* __restrict__ val, int* __restrict__ woff,
                               int2* __restrict__ edges, int nnz) {
    int e = blockIdx.x * blockDim.x + threadIdx.x;
    if (e >= nnz) return;
    int r = row[e];
    int p = atomicAdd(&woff[r], 1);
    edges[p] = make_int2(col[e], __float_as_int(val[e]));
}

// ---------------------------------------------------------------------------
// CSR SpMM, bf16 dense operand, fp32 accumulate. One warp per row.
// out[r][:] = sum_e val[e] * dense[col[e]][:]
// Each lane owns 4 columns: one uint2 (4 x bf16) gather per edge.
// ---------------------------------------------------------------------------
__device__ __forceinline__ void bf4_fma(float4& acc, uint2 u, float v) {
    __nv_bfloat162 lo = *(__nv_bfloat162*)&u.x;
    __nv_bfloat162 hi = *(__nv_bfloat162*)&u.y;
    float2 f0 = __bfloat1622float2(lo);
    float2 f1 = __bfloat1622float2(hi);
    acc.x = fmaf(v, f0.x, acc.x);
    acc.y = fmaf(v, f0.y, acc.y);
    acc.z = fmaf(v, f1.x, acc.z);
    acc.w = fmaf(v, f1.y, acc.w);
}

__global__ void spmm_csr(const int* __restrict__ rptr, const int2* __restrict__ edges,
                         const __nv_bfloat16* __restrict__ dense, float* __restrict__ out,
                         int nrows) {
    int r = blockIdx.x * 8 + (threadIdx.x >> 5);
    int lane = threadIdx.x & 31;
    if (r >= nrows) return;
    int s = rptr[r], e = rptr[r + 1];
    const uint2* d2 = (const uint2*)dense;     // 32 uint2 per row (H=128 bf16)
    float4 acc = make_float4(0.f, 0.f, 0.f, 0.f);
    int i = s;
    for (; i + 4 <= e; i += 4) {
        int2 c0 = edges[i + 0];
        int2 c1 = edges[i + 1];
        int2 c2 = edges[i + 2];
        int2 c3 = edges[i + 3];
        uint2 u0 = d2[(size_t)c0.x * 32 + lane];
        uint2 u1 = d2[(size_t)c1.x * 32 + lane];
        uint2 u2 = d2[(size_t)c2.x * 32 + lane];
        uint2 u3 = d2[(size_t)c3.x * 32 + lane];
        bf4_fma(acc, u0, __int_as_float(c0.y));
        bf4_fma(acc, u1, __int_as_float(c1.y));
        bf4_fma(acc, u2, __int_as_float(c2.y));
        bf4_fma(acc, u3, __int_as_float(c3.y));
    }
    for (; i < e; i++) {
        int2 c = edges[i];
        uint2 u = d2[(size_t)c.x * 32 + lane];
        bf4_fma(acc, u, __int_as_float(c.y));
    }
    ((float4*)out)[(size_t)r * 32 + lane] = acc;
}

// ---------------------------------------------------------------------------
// Dense kernel helpers: 512 threads, 32 rows per block, 2 blocks/SM.
// Thread (h, j): h = tid>>7 (0..3) handles rows [h*8, h*8+8), j = tid&127.
// ---------------------------------------------------------------------------
__device__ __forceinline__ void load_W_sh(float* Wsh, const float* __restrict__ W, int tid) {
    for (int i = tid; i < H * (H / 4); i += TPB_GEMM) {
        int rw = i >> 5;
        int c4 = i & 31;
        float4 w = ((const float4*)W)[i];
        float* p = Wsh + rw * WPAD + c4 * 4;
        p[0] = w.x; p[1] = w.y; p[2] = w.z; p[3] = w.w;
    }
}

__device__ __forceinline__ void load_X_sh(float* xs, const float* __restrict__ X,
                                          int r0, int nr, int tid) {
    for (int i = tid; i < ROWS * (H / 4); i += TPB_GEMM) {
        int rr = i / (H / 4);
        float4 x = make_float4(0.f, 0.f, 0.f, 0.f);
        if (rr < nr) x = ((const float4*)(X + (size_t)r0 * H))[i];
        ((float4*)xs)[i] = x;
    }
}

__device__ __forceinline__ void mma_8(float* acc, const float* Wsh, const float* xs,
                                      int j, int h) {
    const float4* X4 = (const float4*)(xs + h * RPT * H);
#pragma unroll 4
    for (int k4 = 0; k4 < H / 4; k4++) {
        float4 w = ((const float4*)(Wsh + j * WPAD))[k4];
#pragma unroll
        for (int r = 0; r < RPT; r++) {
            float4 x = X4[r * (H / 4) + k4];
            acc[r] += w.x * x.x + w.y * x.y + w.z * x.z + w.w * x.w;
        }
    }
}

// ---------------------------------------------------------------------------
// out(bf16) = relu(X @ W^T)   -- output feeds only the next SpMM
// ---------------------------------------------------------------------------
__global__ __launch_bounds__(TPB_GEMM, 2)
void gemm_relu(const float* __restrict__ X, const float* __restrict__ W,
               __nv_bfloat16* __restrict__ out, int nrows) {
    extern __shared__ float sh[];
    float* Wsh = sh;                   // [H][WPAD]
    float* xs  = sh + H * WPAD;        // [ROWS][H]
    int tid = threadIdx.x;
    int j = tid & 127, h = tid >> 7;

    load_W_sh(Wsh, W, tid);
    int r0 = blockIdx.x * ROWS;
    int nr = min(ROWS, nrows - r0);
    load_X_sh(xs, X, r0, nr, tid);
    __syncthreads();

    float acc[RPT];
#pragma unroll
    for (int r = 0; r < RPT; r++) acc[r] = 0.f;
    mma_8(acc, Wsh, xs, j, h);

#pragma unroll
    for (int r = 0; r < RPT; r++) {
        int gr = h * RPT + r;
        if (gr < nr)
            out[(size_t)(r0 + gr) * H + j] = __float2bfloat16(fmaxf(acc[r], 0.f));
    }
}

// ---------------------------------------------------------------------------
// word_sum(bf16) = layernorm((1-a)*emb + a*relu(Xin @ W2^T)) * g + b + emb
// (+emb folds doc_H0: X@word_H + X@emb = X@(word_H+emb))
// ---------------------------------------------------------------------------
__global__ __launch_bounds__(TPB_GEMM, 2)
void gemm_norm(const float* __restrict__ Xin, const float* __restrict__ W,
               const float* __restrict__ emb, const float* __restrict__ g,
               const float* __restrict__ b, __nv_bfloat16* __restrict__ out, int nrows) {
    extern __shared__ float sh[];
    float* Wsh   = sh;                          // [H][WPAD]
    float* xs    = sh + H * WPAD;               // [ROWS][H], reused as msh
    float* stats = xs + ROWS * H;               // [ROWS][2]
    int tid = threadIdx.x;
    int j = tid & 127, h = tid >> 7;

    load_W_sh(Wsh, W, tid);
    int r0 = blockIdx.x * ROWS;
    int nr = min(ROWS, nrows - r0);
    load_X_sh(xs, Xin, r0, nr, tid);
    __syncthreads();

    float acc[RPT];
#pragma unroll
    for (int r = 0; r < RPT; r++) acc[r] = 0.f;
    mma_8(acc, Wsh, xs, j, h);
    __syncthreads();                            // all reads of xs done

    float* msh = xs;
#pragma unroll
    for (int r = 0; r < RPT; r++) {
        int gr = h * RPT + r;
        float m = 0.f;
        if (gr < nr) {
            float e = emb[(size_t)(r0 + gr) * H + j];
            m = (1.f - ALPHA) * e + ALPHA * fmaxf(acc[r], 0.f);
        }
        msh[gr * H + j] = m;
    }
    __syncthreads();

    // 16 threads per row reduce sum / sumsq (512 threads -> 32 rows)
    int rr = tid >> 4;
    int sub = tid & 15;
    float s = 0.f, s2 = 0.f;
    for (int k = sub; k < H; k += 16) {
        float t = msh[rr * H + k];
        s += t;
        s2 += t * t;
    }
#pragma unroll
    for (int off = 8; off > 0; off >>= 1) {
        s  += __shfl_down_sync(0xffffffffu, s, off, 16);
        s2 += __shfl_down_sync(0xffffffffu, s2, off, 16);
    }
    if (sub == 0) {
        float mu = s * (1.f / H);
        stats[rr * 2 + 0] = mu;
        stats[rr * 2 + 1] = s2 * (1.f / H) - mu * mu;
    }
    __syncthreads();

    float gj = g[j], bj = b[j];
#pragma unroll
    for (int r = 0; r < RPT; r++) {
        int gr = h * RPT + r;
        if (gr < nr) {
            float mu  = stats[gr * 2 + 0];
            float var = stats[gr * 2 + 1];
            float m = msh[gr * H + j];
            float e = emb[(size_t)(r0 + gr) * H + j];
            out[(size_t)(r0 + gr) * H + j] = __float2bfloat16(
                (m - mu) * rsqrtf(var + EPS) * gj + bj + e);
        }
    }
}

// ---------------------------------------------------------------------------
// logits = relu(Xin @ mlpW^T + mlp_b) @ clfW^T + clf_b   ([NDOCS,2] out)
// ---------------------------------------------------------------------------
__global__ __launch_bounds__(TPB_GEMM, 2)
void head_kernel(const float* __restrict__ Xin, const float* __restrict__ mlpW,
                 const float* __restrict__ mlpb, const float* __restrict__ clfW,
                 const float* __restrict__ clfb, float* __restrict__ out, int nrows) {
    extern __shared__ float sh[];
    float* Wsh  = sh;                  // [H][WPAD]
    float* xs   = sh + H * WPAD;       // [ROWS][H], reused as psh0
    float* psh1 = xs + ROWS * H;       // [ROWS][H]
    int tid = threadIdx.x;
    int j = tid & 127, h = tid >> 7;

    load_W_sh(Wsh, mlpW, tid);
    int r0 = blockIdx.x * ROWS;
    int nr = min(ROWS, nrows - r0);
    load_X_sh(xs, Xin, r0, nr, tid);
    __syncthreads();

    float acc[RPT];
#pragma unroll
    for (int r = 0; r < RPT; r++) acc[r] = 0.f;
    mma_8(acc, Wsh, xs, j, h);
    __syncthreads();                   // all reads of xs done

    float* psh0 = xs;
    float bj = mlpb[j];
    float c0 = clfW[j];
    float c1 = clfW[H + j];
#pragma unroll
    for (int r = 0; r < RPT; r++) {
        int gr = h * RPT + r;
        float hh = fmaxf(acc[r] + bj, 0.f);
        psh0[gr * H + j] = hh * c0;
        psh1[gr * H + j] = hh * c1;
    }
    __syncthreads();

    int rr = tid >> 4;
    int sub = tid & 15;
    float s0 = 0.f, s1 = 0.f;
    for (int k = sub; k < H; k += 16) {
        s0 += psh0[rr * H + k];
        s1 += psh1[rr * H + k];
    }
#pragma unroll
    for (int off = 8; off > 0; off >>= 1) {
        s0 += __shfl_down_sync(0xffffffffu, s0, off, 16);
        s1 += __shfl_down_sync(0xffffffffu, s1, off, 16);
    }
    if (sub == 0 && rr < nr) {
        out[(size_t)(r0 + rr) * 2 + 0] = s0 + clfb[0];
        out[(size_t)(r0 + rr) * 2 + 1] = s1 + clfb[1];
    }
}

// ---------------------------------------------------------------------------
extern "C" void kernel_launch(void* const* d_in, const int* in_sizes, int n_in,
                              void* d_out, int out_size) {
    const int*   A_row  = (const int*)d_in[0];
    const int*   A_col  = (const int*)d_in[1];
    const float* A_val  = (const float*)d_in[2];
    const int*   X_row  = (const int*)d_in[3];
    const int*   X_col  = (const int*)d_in[4];
    const float* X_val  = (const float*)d_in[5];
    const float* emb_W  = (const float*)d_in[6];
    const float* lin1_W = (const float*)d_in[7];
    const float* lin2_W = (const float*)d_in[8];
    const float* norm_g = (const float*)d_in[9];
    const float* norm_b = (const float*)d_in[10];
    const float* mlp_W  = (const float*)d_in[11];
    const float* mlp_b  = (const float*)d_in[12];
    const float* clf_W  = (const float*)d_in[13];
    const float* clf_b  = (const float*)d_in[14];
    float* out = (float*)d_out;

    int E_nnz = in_sizes[0];
    int X_nnz = in_sizes[3];

    float *S1, *S3;
    __nv_bfloat16* B1;
    int *rptrA, *rptrX, *cntA, *cntX, *bsumsA, *bsumsX;
    int2 *edgeA, *edgeX;
    cudaGetSymbolAddress((void**)&S1, g_S1);
    cudaGetSymbolAddress((void**)&S3, g_S3);
    cudaGetSymbolAddress((void**)&B1, g_B1);
    cudaGetSymbolAddress((void**)&rptrA,  g_rptrA);
    cudaGetSymbolAddress((void**)&rptrX,  g_rptrX);
    cudaGetSymbolAddress((void**)&cntA,   g_cntA);
    cudaGetSymbolAddress((void**)&cntX,   g_cntX);
    cudaGetSymbolAddress((void**)&bsumsA, g_bsumsA);
    cudaGetSymbolAddress((void**)&bsumsX, g_bsumsX);
    cudaGetSymbolAddress((void**)&edgeA,  g_edgeA);
    cudaGetSymbolAddress((void**)&edgeX,  g_edgeX);

    // Side stream + fork/join events (created once; events carry no timing)
    static cudaStream_t s2 = nullptr;
    static cudaEvent_t e0 = nullptr, e1 = nullptr, e2 = nullptr;
    if (!s2) {
        cudaStreamCreateWithFlags(&s2, cudaStreamNonBlocking);
        cudaEventCreateWithFlags(&e0, cudaEventDisableTiming);
        cudaEventCreateWithFlags(&e1, cudaEventDisableTiming);
        cudaEventCreateWithFlags(&e2, cudaEventDisableTiming);
    }

    size_t smem_gemm = (H * WPAD + ROWS * H) * sizeof(float);
    size_t smem_norm = (H * WPAD + ROWS * H + 2 * ROWS) * sizeof(float);
    size_t smem_head = (H * WPAD + 2 * ROWS * H) * sizeof(float);
    cudaFuncSetAttribute(gemm_relu,   cudaFuncAttributeMaxDynamicSharedMemorySize, (int)smem_gemm);
    cudaFuncSetAttribute(gemm_norm,   cudaFuncAttributeMaxDynamicSharedMemorySize, (int)smem_norm);
    cudaFuncSetAttribute(head_kernel, cudaFuncAttributeMaxDynamicSharedMemorySize, (int)smem_head);

    int nbA = (V + 1023) / 1024;        // 49
    int nbX = (NDOCS + 1023) / 1024;    // 20
    int gEA = (E_nnz + 255) / 256;
    int gEX = (X_nnz + 255) / 256;
    int gV  = (V + ROWS - 1) / ROWS;
    int gD  = (NDOCS + ROWS - 1) / ROWS;
    int gRA = (V + 7) / 8;
    int gRX = (NDOCS + 7) / 8;
    int nC4 = (V * H) / 4;

    // ---- Fork side stream ----
    cudaEventRecord(e0, 0);
    cudaStreamWaitEvent(s2, e0, 0);

    // (s2) emb -> bf16, then build CSR for X (both independent of A chain)
    f2bf_kernel<<<(nC4 + 255) / 256, 256, 0, s2>>>(emb_W, B1, nC4);
    cudaEventRecord(e1, s2);
    cudaMemsetAsync(cntX, 0, (size_t)NDOCS * sizeof(int), s2);
    hist_kernel<<<gEX, 256, 0, s2>>>(X_row, cntX, X_nnz);
    scan1<<<nbX, 1024, 0, s2>>>(cntX, rptrX, bsumsX, NDOCS);
    scan2<<<1, 1024, 0, s2>>>(bsumsX, nbX);
    scan3<<<nbX, 1024, 0, s2>>>(rptrX, bsumsX, cntX, NDOCS, X_nnz);
    scatter_kernel<<<gEX, 256, 0, s2>>>(X_row, X_col, X_val, cntX, edgeX, X_nnz);
    cudaEventRecord(e2, s2);

    // (main) build CSR for A
    cudaMemsetAsync(cntA, 0, (size_t)V * sizeof(int));
    hist_kernel<<<gEA, 256>>>(A_row, cntA, E_nnz);
    scan1<<<nbA, 1024>>>(cntA, rptrA, bsumsA, V);
    scan2<<<1, 1024>>>(bsumsA, nbA);
    scan3<<<nbA, 1024>>>(rptrA, bsumsA, cntA, V, E_nnz);
    scatter_kernel<<<gEA, 256>>>(A_row, A_col, A_val, cntA, edgeA, E_nnz);

    // ---- Pipeline ----
    cudaStreamWaitEvent(0, e1, 0);                       // emb bf16 ready
    // T1 = A @ emb
    spmm_csr<<<gRA, 256>>>(rptrA, edgeA, B1, S1, V);
    // H1(bf16) = relu(T1 @ W1^T)  (B1 reusable: emb copy consumed)
    gemm_relu<<<gV, TPB_GEMM, smem_gemm>>>(S1, lin1_W, B1, V);
    // T2 = A @ H1
    spmm_csr<<<gRA, 256>>>(rptrA, edgeA, B1, S1, V);
    // word_sum(bf16) = layernorm(mix(emb, relu(T2 @ W2^T))) + emb
    gemm_norm<<<gV, TPB_GEMM, smem_norm>>>(S1, lin2_W, emb_W, norm_g, norm_b, B1, V);
    cudaStreamWaitEvent(0, e2, 0);                       // X CSR ready
    // doc = X @ word_sum
    spmm_csr<<<gRX, 256>>>(rptrX, edgeX, B1, S3, NDOCS);
    // logits
    head_kernel<<<gD, TPB_GEMM, smem_head>>>(S3, mlp_W, mlp_b, clf_W, clf_b, out, NDOCS);
}